// round 3
// baseline (speedup 1.0000x reference)
#include <cuda_runtime.h>
#include <math.h>

// DiceLoss: logits [8,19,512,512] f32, targets [8,512,512] int32 (harness downcasts i64)
#define NC 19
#define HW4 65536LL   // (512*512)/4 float4-groups per image-channel

// Scratch: probs_sum[0..18], inter[19..37], cnt[38..56], valid_count[57]
__device__ float g_acc[3 * NC + 1];
__device__ unsigned int g_done;

__global__ __launch_bounds__(256, 2) void dice_fused_kernel(
    const float* __restrict__ logits,
    const int* __restrict__ targets,
    long long npix,
    float* __restrict__ out)
{
    __shared__ float s_inter[NC];
    __shared__ float s_cnt[NC];
    __shared__ float s_psum[NC];
    __shared__ float s_valid;
    __shared__ int   s_last;

    const int tid = threadIdx.x;
    if (tid < NC) { s_inter[tid] = 0.0f; s_cnt[tid] = 0.0f; s_psum[tid] = 0.0f; }
    if (tid == 0) s_valid = 0.0f;
    __syncthreads();

    float acc[NC];
#pragma unroll
    for (int c = 0; c < NC; c++) acc[c] = 0.0f;
    float vcnt = 0.0f;

    const long long npix4 = npix >> 2;
    const float4* __restrict__ lg4 = (const float4*)logits;
    const int4*   __restrict__ tg4 = (const int4*)targets;
    const long long stride = (long long)gridDim.x * blockDim.x;

    for (long long p = (long long)blockIdx.x * blockDim.x + tid; p < npix4; p += stride) {
        const int4 t = tg4[p];
        const long long b  = p >> 16;           // p / HW4
        const long long hw = p & (HW4 - 1);     // p % HW4
        const float4* __restrict__ base = lg4 + b * (long long)NC * HW4 + hw;

        float4 e[NC];
#pragma unroll
        for (int c = 0; c < NC; c++) e[c] = base[(long long)c * HW4];

        float4 s = make_float4(0.f, 0.f, 0.f, 0.f);
#pragma unroll
        for (int c = 0; c < NC; c++) {
            e[c].x = __expf(e[c].x); s.x += e[c].x;
            e[c].y = __expf(e[c].y); s.y += e[c].y;
            e[c].z = __expf(e[c].z); s.z += e[c].z;
            e[c].w = __expf(e[c].w); s.w += e[c].w;
        }

        const bool v0 = (unsigned)t.x < NC;
        const bool v1 = (unsigned)t.y < NC;
        const bool v2 = (unsigned)t.z < NC;
        const bool v3 = (unsigned)t.w < NC;

        // Fold validity into the normalization: masked probs everywhere.
        float4 inv;
        inv.x = v0 ? __frcp_rn(s.x) : 0.0f;
        inv.y = v1 ? __frcp_rn(s.y) : 0.0f;
        inv.z = v2 ? __frcp_rn(s.z) : 0.0f;
        inv.w = v3 ? __frcp_rn(s.w) : 0.0f;

        float g0 = 0.f, g1 = 0.f, g2 = 0.f, g3 = 0.f;
#pragma unroll
        for (int c = 0; c < NC; c++) {
            const float px = e[c].x * inv.x;
            const float py = e[c].y * inv.y;
            const float pz = e[c].z * inv.z;
            const float pw = e[c].w * inv.w;
            acc[c] += (px + py) + (pz + pw);
            if (c == t.x) g0 = px;
            if (c == t.y) g1 = py;
            if (c == t.z) g2 = pz;
            if (c == t.w) g3 = pw;
        }
        vcnt += (v0 ? 1.f : 0.f) + (v1 ? 1.f : 0.f) + (v2 ? 1.f : 0.f) + (v3 ? 1.f : 0.f);
        if (v0) { atomicAdd(&s_inter[t.x], g0); atomicAdd(&s_cnt[t.x], 1.f); }
        if (v1) { atomicAdd(&s_inter[t.y], g1); atomicAdd(&s_cnt[t.y], 1.f); }
        if (v2) { atomicAdd(&s_inter[t.z], g2); atomicAdd(&s_cnt[t.z], 1.f); }
        if (v3) { atomicAdd(&s_inter[t.w], g3); atomicAdd(&s_cnt[t.w], 1.f); }
    }

    // Scalar tail (npix not divisible by 4) — one thread, at most 3 pixels.
    if (blockIdx.x == 0 && tid == 0) {
        for (long long p = npix4 << 2; p < npix; p++) {
            const int t = targets[p];
            if ((unsigned)t >= NC) continue;
            const long long b  = p >> 18;
            const long long hw = p & ((1LL << 18) - 1);
            const float* base = logits + b * (long long)NC * (HW4 * 4) + hw;
            float e[NC]; float s = 0.f;
#pragma unroll
            for (int c = 0; c < NC; c++) { e[c] = __expf(base[(long long)c * HW4 * 4]); s += e[c]; }
            const float inv = __frcp_rn(s);
#pragma unroll
            for (int c = 0; c < NC; c++) acc[c] += e[c] * inv;
            vcnt += 1.f;
            atomicAdd(&s_inter[t], e[t] * inv);
            atomicAdd(&s_cnt[t], 1.f);
        }
    }

    // Warp-reduce register accumulators, one shared atomic per warp per class.
#pragma unroll
    for (int c = 0; c < NC; c++) {
        float v = acc[c];
#pragma unroll
        for (int o = 16; o > 0; o >>= 1) v += __shfl_xor_sync(0xffffffffu, v, o);
        if ((tid & 31) == 0) atomicAdd(&s_psum[c], v);
    }
    {
        float v = vcnt;
#pragma unroll
        for (int o = 16; o > 0; o >>= 1) v += __shfl_xor_sync(0xffffffffu, v, o);
        if ((tid & 31) == 0) atomicAdd(&s_valid, v);
    }
    __syncthreads();

    // One global atomic per class per block.
    if (tid < NC) {
        atomicAdd(&g_acc[tid],          s_psum[tid]);
        atomicAdd(&g_acc[NC + tid],     s_inter[tid]);
        atomicAdd(&g_acc[2 * NC + tid], s_cnt[tid]);
    }
    if (tid == 0) atomicAdd(&g_acc[3 * NC], s_valid);

    // Last-block-done: finalize + reset scratch for the next (graph-replayed) call.
    __threadfence();
    if (tid == 0) {
        unsigned prev = atomicAdd(&g_done, 1u);
        s_last = (prev == gridDim.x - 1) ? 1 : 0;
    }
    __syncthreads();

    if (s_last) {
        if (tid < 32) {
            float contrib = 0.0f;
            float psum = 0.f, inter = 0.f, cnt = 0.f;
            if (tid < NC) {
                // atomic reads bypass potentially-stale L1
                psum  = atomicAdd(&g_acc[tid], 0.0f);
                inter = atomicAdd(&g_acc[NC + tid], 0.0f);
                cnt   = atomicAdd(&g_acc[2 * NC + tid], 0.0f);
                contrib = 1.0f - (2.0f * inter + 1.0f) / (psum + cnt + 1.0f);
            }
#pragma unroll
            for (int o = 16; o > 0; o >>= 1) contrib += __shfl_xor_sync(0xffffffffu, contrib, o);
            if (tid == 0) {
                const float valid = atomicAdd(&g_acc[3 * NC], 0.0f);
                out[0] = (valid > 0.0f) ? (contrib / (float)NC) : 0.0f;
            }
        }
        __syncthreads();
        if (tid < 3 * NC + 1) g_acc[tid] = 0.0f;
        if (tid == 0) g_done = 0u;
    }
}

extern "C" void kernel_launch(void* const* d_in, const int* in_sizes, int n_in,
                              void* d_out, int out_size) {
    const float* logits  = (const float*)d_in[0];
    const int*   targets = (const int*)d_in[1];
    float* out = (float*)d_out;

    const long long npix = (long long)in_sizes[1];   // B*H*W = 2,097,152

    dice_fused_kernel<<<296, 256>>>(logits, targets, npix, out);
}

// round 4
// speedup vs baseline: 1.2792x; 1.2792x over previous
#include <cuda_runtime.h>
#include <math.h>

// DiceLoss: logits [8,19,512,512] f32, targets [8,512,512] int32 (harness downcasts i64)
#define NC 19
#define HW2 131072LL   // (512*512)/2 float2-pairs per image-channel

// Scratch: probs_sum[0..18], inter[19..37], cnt[38..56], valid_count[57]
__device__ float g_acc[3 * NC + 1];
__device__ unsigned int g_done;

__global__ __launch_bounds__(128, 6) void dice_fused_kernel(
    const float* __restrict__ logits,
    const int* __restrict__ targets,
    long long npix,
    float* __restrict__ out)
{
    __shared__ float s_inter[NC];
    __shared__ float s_cnt[NC];
    __shared__ float s_psum[NC];
    __shared__ float s_valid;
    __shared__ int   s_last;

    const int tid = threadIdx.x;
    if (tid < NC) { s_inter[tid] = 0.0f; s_cnt[tid] = 0.0f; s_psum[tid] = 0.0f; }
    if (tid == 0) s_valid = 0.0f;
    __syncthreads();

    float acc[NC];
#pragma unroll
    for (int c = 0; c < NC; c++) acc[c] = 0.0f;
    float vcnt = 0.0f;

    const long long npix2 = npix >> 1;
    const float2* __restrict__ lg2 = (const float2*)logits;
    const int2*   __restrict__ tg2 = (const int2*)targets;
    const long long stride = (long long)gridDim.x * blockDim.x;

    for (long long p = (long long)blockIdx.x * blockDim.x + tid; p < npix2; p += stride) {
        const int2 t = tg2[p];
        const long long b  = p >> 17;           // p / HW2
        const long long hw = p & (HW2 - 1);     // p % HW2
        const float2* __restrict__ base = lg2 + b * (long long)NC * HW2 + hw;

        float2 e[NC];
#pragma unroll
        for (int c = 0; c < NC; c++) e[c] = base[(long long)c * HW2];

        float sx = 0.f, sy = 0.f;
#pragma unroll
        for (int c = 0; c < NC; c++) {
            e[c].x = __expf(e[c].x); sx += e[c].x;
            e[c].y = __expf(e[c].y); sy += e[c].y;
        }

        const bool v0 = (unsigned)t.x < NC;
        const bool v1 = (unsigned)t.y < NC;

        // Fold validity into the normalization: masked probs everywhere.
        const float invx = v0 ? __frcp_rn(sx) : 0.0f;
        const float invy = v1 ? __frcp_rn(sy) : 0.0f;

        float g0 = 0.f, g1 = 0.f;
#pragma unroll
        for (int c = 0; c < NC; c++) {
            const float px = e[c].x * invx;
            const float py = e[c].y * invy;
            acc[c] += px + py;
            if (c == t.x) g0 = px;
            if (c == t.y) g1 = py;
        }
        vcnt += (v0 ? 1.f : 0.f) + (v1 ? 1.f : 0.f);
        if (v0) { atomicAdd(&s_inter[t.x], g0); atomicAdd(&s_cnt[t.x], 1.f); }
        if (v1) { atomicAdd(&s_inter[t.y], g1); atomicAdd(&s_cnt[t.y], 1.f); }
    }

    // Scalar tail (npix odd) — one thread, at most 1 pixel.
    if (blockIdx.x == 0 && tid == 0) {
        for (long long p = npix2 << 1; p < npix; p++) {
            const int t = targets[p];
            if ((unsigned)t >= NC) continue;
            const long long b  = p >> 18;
            const long long hw = p & ((1LL << 18) - 1);
            const float* base = logits + b * (long long)NC * (HW2 * 2) + hw;
            float e[NC]; float s = 0.f;
#pragma unroll
            for (int c = 0; c < NC; c++) { e[c] = __expf(base[(long long)c * HW2 * 2]); s += e[c]; }
            const float inv = __frcp_rn(s);
#pragma unroll
            for (int c = 0; c < NC; c++) acc[c] += e[c] * inv;
            vcnt += 1.f;
            atomicAdd(&s_inter[t], e[t] * inv);
            atomicAdd(&s_cnt[t], 1.f);
        }
    }

    // Warp-reduce register accumulators, one shared atomic per warp per class.
#pragma unroll
    for (int c = 0; c < NC; c++) {
        float v = acc[c];
#pragma unroll
        for (int o = 16; o > 0; o >>= 1) v += __shfl_xor_sync(0xffffffffu, v, o);
        if ((tid & 31) == 0) atomicAdd(&s_psum[c], v);
    }
    {
        float v = vcnt;
#pragma unroll
        for (int o = 16; o > 0; o >>= 1) v += __shfl_xor_sync(0xffffffffu, v, o);
        if ((tid & 31) == 0) atomicAdd(&s_valid, v);
    }
    __syncthreads();

    // One global atomic per class per block.
    if (tid < NC) {
        atomicAdd(&g_acc[tid],          s_psum[tid]);
        atomicAdd(&g_acc[NC + tid],     s_inter[tid]);
        atomicAdd(&g_acc[2 * NC + tid], s_cnt[tid]);
    }
    if (tid == 0) atomicAdd(&g_acc[3 * NC], s_valid);

    // Last-block-done: finalize + reset scratch for the next (graph-replayed) call.
    __threadfence();
    if (tid == 0) {
        unsigned prev = atomicAdd(&g_done, 1u);
        s_last = (prev == gridDim.x - 1) ? 1 : 0;
    }
    __syncthreads();

    if (s_last) {
        if (tid < 32) {
            float contrib = 0.0f;
            if (tid < NC) {
                // atomic reads bypass potentially-stale L1
                const float psum  = atomicAdd(&g_acc[tid], 0.0f);
                const float inter = atomicAdd(&g_acc[NC + tid], 0.0f);
                const float cnt   = atomicAdd(&g_acc[2 * NC + tid], 0.0f);
                contrib = 1.0f - (2.0f * inter + 1.0f) / (psum + cnt + 1.0f);
            }
#pragma unroll
            for (int o = 16; o > 0; o >>= 1) contrib += __shfl_xor_sync(0xffffffffu, contrib, o);
            if (tid == 0) {
                const float valid = atomicAdd(&g_acc[3 * NC], 0.0f);
                out[0] = (valid > 0.0f) ? (contrib / (float)NC) : 0.0f;
            }
        }
        __syncthreads();
        if (tid < 3 * NC + 1) g_acc[tid] = 0.0f;
        if (tid == 0) g_done = 0u;
    }
}

extern "C" void kernel_launch(void* const* d_in, const int* in_sizes, int n_in,
                              void* d_out, int out_size) {
    const float* logits  = (const float*)d_in[0];
    const int*   targets = (const int*)d_in[1];
    float* out = (float*)d_out;

    const long long npix = (long long)in_sizes[1];   // B*H*W = 2,097,152

    dice_fused_kernel<<<888, 128>>>(logits, targets, npix, out);
}